// round 17
// baseline (speedup 1.0000x reference)
#include <cuda_runtime.h>
#include <cuda_bf16.h>
#include <cuda_fp16.h>
#include <math.h>
#include <stdint.h>

#define SEQ    4096
#define HID    4096
#define NHEADS 32
#define NKV    8
#define HD     128

// ---------------- device scratch (allocation-free rule) ----------------
// QKV proj output: 48 head slots (Q:0-31, K:32-39, V:40-47), fp32
__device__ float  g_QKV[(size_t)48 * SEQ * HD];
__device__ __half g_Ah[(size_t)SEQ * HID];              // flash out (fp16)
__device__ __half g_hH[(size_t)SEQ * HID];              // fp16-rounded operands
__device__ __half g_hWqkv[(size_t)(HID + 2 * NKV * HD) * HID];  // Wq|Wk|Wv
__device__ __half g_hWo[(size_t)HID * HID];
__device__ __half g_Kh[(size_t)NKV * SEQ * HD];         // K fp16 (post-rope)
__device__ __half g_Vh[(size_t)NKV * SEQ * HD];         // V fp16

__device__ __forceinline__ float ex2a(float x) {
    float y;
    asm("ex2.approx.f32 %0, %1;" : "=f"(y) : "f"(x));
    return y;
}
__device__ __forceinline__ uint32_t h2ex2(uint32_t x) {   // packed fp16x2 exp2
    uint32_t y;
    asm("ex2.approx.f16x2 %0, %1;" : "=r"(y) : "r"(x));
    return y;
}
__device__ __forceinline__ float rcpa(float x) {
    float y;
    asm("rcp.approx.f32 %0, %1;" : "=f"(y) : "f"(x));
    return y;
}
__device__ __forceinline__ void cp16(uint32_t dst, const void* src) {
    asm volatile("cp.async.cg.shared.global [%0], [%1], 16;"
                 :: "r"(dst), "l"(src) : "memory");
}
__device__ __forceinline__ void cp_commit() {
    asm volatile("cp.async.commit_group;" ::: "memory");
}

// ---------------------------------------------------------------------------
// Pre-round fp32 -> fp16 (rn)
// ---------------------------------------------------------------------------
__global__ __launch_bounds__(256) void round_f16(const float4* __restrict__ in,
                                                 __half2* __restrict__ out, int n4)
{
    int i = blockIdx.x * blockDim.x + threadIdx.x;
    if (i >= n4) return;
    float4 v = in[i];
    out[2 * i]     = __halves2half2(__float2half_rn(v.x), __float2half_rn(v.y));
    out[2 * i + 1] = __halves2half2(__float2half_rn(v.z), __float2half_rn(v.w));
}

// ---------------------------------------------------------------------------
// ldmatrix / mma helpers
// ---------------------------------------------------------------------------
__device__ __forceinline__ void ldsm4(uint32_t a[4], uint32_t addr) {
    asm volatile("ldmatrix.sync.aligned.m8n8.x4.shared.b16 {%0,%1,%2,%3}, [%4];"
        : "=r"(a[0]), "=r"(a[1]), "=r"(a[2]), "=r"(a[3]) : "r"(addr));
}
__device__ __forceinline__ void ldsm4t(uint32_t a[4], uint32_t addr) {
    asm volatile("ldmatrix.sync.aligned.m8n8.x4.trans.shared.b16 {%0,%1,%2,%3}, [%4];"
        : "=r"(a[0]), "=r"(a[1]), "=r"(a[2]), "=r"(a[3]) : "r"(addr));
}
__device__ __forceinline__ void mma_f16(float c[4], const uint32_t a[4],
                                        uint32_t b0, uint32_t b1) {
    asm volatile(
        "mma.sync.aligned.m16n8k16.row.col.f32.f16.f16.f32 "
        "{%0,%1,%2,%3}, {%4,%5,%6,%7}, {%8,%9}, {%0,%1,%2,%3};"
        : "+f"(c[0]), "+f"(c[1]), "+f"(c[2]), "+f"(c[3])
        : "r"(a[0]), "r"(a[1]), "r"(a[2]), "r"(a[3]), "r"(b0), "r"(b1));
}
__device__ __forceinline__ uint32_t pack_f16(float lo, float hi) {
    uint32_t r;
    asm("cvt.rn.f16x2.f32 %0, %1, %2;" : "=r"(r) : "f"(hi), "f"(lo));
    return r;
}

// ---------------------------------------------------------------------------
// FP16 GEMM (R12 skeleton): C = A(MxK) * B(NxK)^T, fp32 accum.
// CTA 128x256, K-tile 64, 3-stage cp.async, one sync per iter.
// mode 0: C[row*N+col] ; mode 1: head scatter C[((col>>7)*M+row)*128+(col&127)]
// ---------------------------------------------------------------------------
#define GH_A_B  (128 * 144)
#define GH_B_B  (256 * 144)
#define GH_ST   (GH_A_B + GH_B_B)         // 55296 B
#define G_SMEM  (3 * GH_ST)               // 165888 B

__device__ __forceinline__ void g_fill_h(uint32_t smb, int buf,
    const __half* __restrict__ A, const __half* __restrict__ B,
    int bm, int bn, int K, int kt, int tid)
{
    const uint32_t sa = smb + buf * GH_ST;
    const uint32_t sb = sa + GH_A_B;
    const size_t kof = (size_t)kt << 6;
    for (int i = tid; i < 1024; i += 256) {
        int row = i >> 3, ch = (i & 7) << 4;
        cp16(sa + row * 144 + ch,
             (const char*)(A + (size_t)(bm + row) * K + kof) + ch);
    }
    for (int i = tid; i < 2048; i += 256) {
        int row = i >> 3, ch = (i & 7) << 4;
        cp16(sb + row * 144 + ch,
             (const char*)(B + (size_t)(bn + row) * K + kof) + ch);
    }
    cp_commit();
}

__global__ __launch_bounds__(256, 1) void gemm_f16(
    const __half* __restrict__ A, const __half* __restrict__ B,
    float* __restrict__ C, int M, int N, int K, int mode)
{
    extern __shared__ __align__(16) char sm[];
    const uint32_t smb = (uint32_t)__cvta_generic_to_shared(sm);

    const int tid  = threadIdx.x;
    const int warp = tid >> 5;
    const int lane = tid & 31;
    const int wm   = warp & 1;
    const int wn   = warp >> 1;
    const int g    = lane >> 2;
    const int t4   = lane & 3;
    const int bm   = blockIdx.y * 128;
    const int bn   = blockIdx.x * 256;

    const int a_rl  = lane & 15;
    const int a_cl  = (lane >> 4) << 3;
    const int b_rl  = (lane & 7) + (((lane >> 4) & 1) << 3);
    const int b_cl  = ((lane >> 3) & 1) << 3;

    float acc[4][8][4];
#pragma unroll
    for (int mt = 0; mt < 4; mt++)
#pragma unroll
        for (int nt = 0; nt < 8; nt++)
#pragma unroll
            for (int c = 0; c < 4; c++) acc[mt][nt][c] = 0.f;

    const int KT = K >> 6;
    g_fill_h(smb, 0, A, B, bm, bn, K, 0, tid);
    g_fill_h(smb, 1, A, B, bm, bn, K, 1, tid);

    int buf = 0;
    for (int kt = 0; kt < KT; kt++) {
        if (kt < KT - 1) {
            asm volatile("cp.async.wait_group 1;" ::: "memory");
        } else {
            asm volatile("cp.async.wait_group 0;" ::: "memory");
        }
        __syncthreads();
        if (kt + 2 < KT) {
            int nb = buf + 2; if (nb >= 3) nb -= 3;
            g_fill_h(smb, nb, A, B, bm, bn, K, kt + 2, tid);
        }

        const uint32_t sa = smb + buf * GH_ST;
        const uint32_t sb = sa + GH_A_B;

#pragma unroll
        for (int ks = 0; ks < 4; ks++) {
            uint32_t af[4][4];
#pragma unroll
            for (int mt = 0; mt < 4; mt++) {
                uint32_t r = wm * 64 + mt * 16 + a_rl;
                ldsm4(af[mt], sa + (r * 72 + ks * 16 + a_cl) * 2);
            }
#pragma unroll
            for (int jp = 0; jp < 4; jp++) {
                uint32_t bf[4];
                uint32_t r = wn * 64 + jp * 16 + b_rl;
                ldsm4(bf, sb + (r * 72 + ks * 16 + b_cl) * 2);
#pragma unroll
                for (int mt = 0; mt < 4; mt++) {
                    mma_f16(acc[mt][2 * jp],     af[mt], bf[0], bf[1]);
                    mma_f16(acc[mt][2 * jp + 1], af[mt], bf[2], bf[3]);
                }
            }
        }
        if (++buf == 3) buf = 0;
    }

#pragma unroll
    for (int mt = 0; mt < 4; mt++) {
#pragma unroll
        for (int nt = 0; nt < 8; nt++) {
            int row = bm + wm * 64 + mt * 16 + g;
            int col = bn + wn * 64 + nt * 8 + 2 * t4;
            if (mode == 0) {
                *(float2*)(C + (size_t)row * N + col) =
                    make_float2(acc[mt][nt][0], acc[mt][nt][1]);
                *(float2*)(C + (size_t)(row + 8) * N + col) =
                    make_float2(acc[mt][nt][2], acc[mt][nt][3]);
            } else {
                int h = col >> 7, d = col & 127;
                *(float2*)(C + ((size_t)h * M + row) * HD + d) =
                    make_float2(acc[mt][nt][0], acc[mt][nt][1]);
                *(float2*)(C + ((size_t)h * M + row + 8) * HD + d) =
                    make_float2(acc[mt][nt][2], acc[mt][nt][3]);
            }
        }
    }
}

// ---------------------------------------------------------------------------
// RoPE: Q in place (fp32); K -> fp16 global
// ---------------------------------------------------------------------------
__global__ __launch_bounds__(256) void rope_kernel(float* __restrict__ Q,
                                                   const float* __restrict__ Kc,
                                                   __half* __restrict__ Kh,
                                                   const int* __restrict__ pos)
{
    int idx = blockIdx.x * blockDim.x + threadIdx.x;
    int d = idx & 63;
    int s = (idx >> 6) & (SEQ - 1);
    int h = idx >> 18;

    double ang = (double)pos[s] * exp(-(double)d * (9.210340371976184 / 64.0));
    float c  = (float)cos(ang);
    float si = (float)sin(ang);

    if (h < NHEADS) {
        float* base = Q + ((size_t)h * SEQ + s) * HD;
        float x1 = base[d], x2 = base[d + 64];
        base[d]      = x1 * c - x2 * si;
        base[d + 64] = x2 * c + x1 * si;
    } else {
        size_t o = ((size_t)(h - NHEADS) * SEQ + s) * HD;
        float x1 = Kc[o + d], x2 = Kc[o + d + 64];
        Kh[o + d]      = __float2half_rn(x1 * c - x2 * si);
        Kh[o + d + 64] = __float2half_rn(x2 * c + x1 * si);
    }
}

// ---------------------------------------------------------------------------
// flash v3: q-tile 128, kv-tile 128, 256 thr, 1 CTA/SM (255 regs, no spill),
// double-buffered KV (fill issued post-sync, hidden under compute).
// S = Qh*Kh, O += Ph*Vh; softmax via fp16x2 ex2 + ones-mma row sums.
// ---------------------------------------------------------------------------
#define LDB 136
#define ONES16 0x3C003C00u

#define F_QT_B  (128 * LDB * 2)          // 34816
#define F_KT_B  (128 * LDB * 2)          // 34816 (128-row tile)
#define F_STG_B (2 * F_KT_B)             // 69632 (Kh, Vh)
#define F_SMEM  (F_QT_B + 2 * F_STG_B)   // 174080 -> 1 CTA/SM

__device__ __forceinline__ void f_fill(uint32_t stg,
    const __half* Kh_g, const __half* Vh_g, int kvh, int kb, int tid)
{
    const size_t gof = ((size_t)kvh * SEQ + (size_t)kb * 128) * HD;
    const char* kh = (const char*)(Kh_g + gof);
    const char* vh = (const char*)(Vh_g + gof);
    for (int i = tid; i < 2048; i += 256) {     // 128 rows x 16 chunks(16B)
        int row = i >> 4, ch = (i & 15) << 4;
        uint32_t dst = row * (LDB * 2) + ch;
        int src = row * 256 + ch;
        cp16(stg + dst,           kh + src);
        cp16(stg + F_KT_B + dst,  vh + src);
    }
    cp_commit();
}

__global__ __launch_bounds__(256, 1) void flash_v3(
    const float* __restrict__ Q,
    const __half* __restrict__ Kh_g, const __half* __restrict__ Vh_g,
    __half* __restrict__ Out)
{
    extern __shared__ __align__(16) char smem_raw[];
    const uint32_t smb  = (uint32_t)__cvta_generic_to_shared(smem_raw);
    const uint32_t q_h  = smb;
    const uint32_t stg0 = smb + F_QT_B;

    const int tid  = threadIdx.x;
    const int wid  = tid >> 5;
    const int lane = tid & 31;
    const int g    = lane >> 2;
    const int t    = lane & 3;
    const int qb   = gridDim.x - 1 - blockIdx.x;   // big blocks first
    const int h    = blockIdx.y;
    const int kvh  = h >> 2;

    const int nkb = qb + 1;
    f_fill(stg0, Kh_g, Vh_g, kvh, 0, tid);

    {
        const float4* Q4 = (const float4*)(Q + ((size_t)h * SEQ + (size_t)qb * 128) * HD);
        __half* Qh = (__half*)smem_raw;
        for (int f = tid; f < 4096; f += 256) {
            int row = f >> 5, d0 = (f & 31) << 2;
            float4 q = Q4[f];
            int o = row * LDB + d0;
            *(__half2*)&Qh[o]     = __halves2half2(__float2half_rn(q.x),
                                                   __float2half_rn(q.y));
            *(__half2*)&Qh[o + 2] = __halves2half2(__float2half_rn(q.z),
                                                   __float2half_rn(q.w));
        }
    }

    const int a_row = wid * 16 + (lane & 15);
    const int a_col = (lane >> 4) << 3;
    const int kb_row = (lane & 7) + (((lane >> 4) & 1) << 3);
    const int kb_col = ((lane >> 3) & 1) << 3;
    const int v_row  = (lane & 7) + (((lane >> 3) & 1) << 3);
    const int v_col  = (lane >> 4) << 3;

    float o_[16][4];
    float m0 = -INFINITY, m1 = -INFINITY, l0 = 0.f, l1 = 0.f;
#pragma unroll
    for (int j = 0; j < 16; j++)
#pragma unroll
        for (int c = 0; c < 4; c++) o_[j][c] = 0.f;

    const float scale2 = 0.12751791437073365f;   // 1/sqrt(128) * log2(e)
    const int rl0 = wid * 16 + g;
    const int rl1 = rl0 + 8;

    for (int kb = 0; kb < nkb; kb++) {
        const int buf = kb & 1;
        asm volatile("cp.async.wait_group 0;" ::: "memory");
        __syncthreads();                 // fill(kb) visible, prior reads done
        if (kb + 1 < nkb)
            f_fill(stg0 + (buf ^ 1) * F_STG_B, Kh_g, Vh_g, kvh, kb + 1, tid);

        const int kofs = (kb - qb) * 128;       // key col - q row offset
        if (kofs <= wid * 16 + 15) {            // warp not fully masked
            const uint32_t kh_s = stg0 + buf * F_STG_B;
            const uint32_t vh_s = kh_s + F_KT_B;

            float sc[16][4];
#pragma unroll
            for (int j = 0; j < 16; j++)
#pragma unroll
                for (int c = 0; c < 4; c++) sc[j][c] = 0.f;

#pragma unroll
            for (int ks = 0; ks < 8; ks++) {
                uint32_t ahf[4];
                uint32_t aoff = ((a_row * LDB) + (ks * 16 + a_col)) * 2;
                ldsm4(ahf, q_h + aoff);
#pragma unroll
                for (int jp = 0; jp < 8; jp++) {
                    uint32_t bh[4];
                    uint32_t boff = (((jp * 16 + kb_row) * LDB)
                                     + (ks * 16 + kb_col)) * 2;
                    ldsm4(bh, kh_s + boff);
                    mma_f16(sc[2 * jp],     ahf, bh[0], bh[1]);
                    mma_f16(sc[2 * jp + 1], ahf, bh[2], bh[3]);
                }
            }

            // ---- mask + running max (raw score domain) ----
            const bool diag = (kofs + 127 > rl0);
            float tm0 = -INFINITY, tm1 = -INFINITY;
#pragma unroll
            for (int j = 0; j < 16; j++) {
                float v0 = sc[j][0], v1 = sc[j][1];
                float v2 = sc[j][2], v3 = sc[j][3];
                if (diag) {
                    int c0 = kofs + 8 * j + 2 * t;
                    if (c0     > rl0) v0 = -INFINITY;
                    if (c0 + 1 > rl0) v1 = -INFINITY;
                    if (c0     > rl1) v2 = -INFINITY;
                    if (c0 + 1 > rl1) v3 = -INFINITY;
                }
                sc[j][0] = v0; sc[j][1] = v1; sc[j][2] = v2; sc[j][3] = v3;
                tm0 = fmaxf(tm0, fmaxf(v0, v1));
                tm1 = fmaxf(tm1, fmaxf(v2, v3));
            }
            tm0 = fmaxf(tm0, __shfl_xor_sync(0xffffffffu, tm0, 1));
            tm0 = fmaxf(tm0, __shfl_xor_sync(0xffffffffu, tm0, 2));
            tm1 = fmaxf(tm1, __shfl_xor_sync(0xffffffffu, tm1, 1));
            tm1 = fmaxf(tm1, __shfl_xor_sync(0xffffffffu, tm1, 2));

            float mn0 = fmaxf(m0, tm0), mn1 = fmaxf(m1, tm1);
            float al0 = ex2a((m0 - mn0) * scale2);
            float al1 = ex2a((m1 - mn1) * scale2);
            m0 = mn0; m1 = mn1;
            const float b0 = -mn0 * scale2;
            const float b1 = -mn1 * scale2;

            // ---- probs via packed fp16x2 exp2 ----
            uint32_t pa[8][4];
#pragma unroll
            for (int kc = 0; kc < 8; kc++) {
                int j0 = 2 * kc, j1 = j0 + 1;
                pa[kc][0] = h2ex2(pack_f16(fmaf(sc[j0][0], scale2, b0),
                                           fmaf(sc[j0][1], scale2, b0)));
                pa[kc][1] = h2ex2(pack_f16(fmaf(sc[j0][2], scale2, b1),
                                           fmaf(sc[j0][3], scale2, b1)));
                pa[kc][2] = h2ex2(pack_f16(fmaf(sc[j1][0], scale2, b0),
                                           fmaf(sc[j1][1], scale2, b0)));
                pa[kc][3] = h2ex2(pack_f16(fmaf(sc[j1][2], scale2, b1),
                                           fmaf(sc[j1][3], scale2, b1)));
            }

            // ---- row sums of the SAME fp16 probs via ones-mma ----
            float lsum[4] = {0.f, 0.f, 0.f, 0.f};
#pragma unroll
            for (int kc = 0; kc < 8; kc++)
                mma_f16(lsum, pa[kc], ONES16, ONES16);
            l0 = l0 * al0 + lsum[0];
            l1 = l1 * al1 + lsum[2];

#pragma unroll
            for (int j = 0; j < 16; j++) {
                o_[j][0] *= al0; o_[j][1] *= al0;
                o_[j][2] *= al1; o_[j][3] *= al1;
            }

            // ---- O += P V ----
#pragma unroll
            for (int kc = 0; kc < 8; kc++) {
#pragma unroll
                for (int jp = 0; jp < 8; jp++) {
                    uint32_t vh[4];
                    uint32_t voff = (((kc * 16 + v_row) * LDB)
                                     + (jp * 16 + v_col)) * 2;
                    ldsm4t(vh, vh_s + voff);
                    mma_f16(o_[2 * jp],     pa[kc], vh[0], vh[1]);
                    mma_f16(o_[2 * jp + 1], pa[kc], vh[2], vh[3]);
                }
            }
        }
    }

    // write out as fp16 (consumed by fp16 O-proj)
    float inv0 = rcpa(l0), inv1 = rcpa(l1);
    size_t r0 = (size_t)qb * 128 + wid * 16 + g;
    __half* base0 = Out + r0 * HID + (size_t)h * HD;
    __half* base1 = base0 + (size_t)8 * HID;
#pragma unroll
    for (int j = 0; j < 16; j++) {
        int col = 8 * j + 2 * t;
        *(__half2*)(base0 + col) =
            __halves2half2(__float2half_rn(o_[j][0] * inv0),
                           __float2half_rn(o_[j][1] * inv0));
        *(__half2*)(base1 + col) =
            __halves2half2(__float2half_rn(o_[j][2] * inv1),
                           __float2half_rn(o_[j][3] * inv1));
    }
}

// ---------------------------------------------------------------------------
extern "C" void kernel_launch(void* const* d_in, const int* in_sizes, int n_in,
                              void* d_out, int out_size)
{
    const float* Hs = (const float*)d_in[0];
    const float* Wq = (const float*)d_in[1];
    const float* Wk = (const float*)d_in[2];
    const float* Wv = (const float*)d_in[3];
    const float* Wo = (const float*)d_in[4];
    const int*  pos = (const int*)d_in[5];
    float* out = (float*)d_out;

    float* QKVp;
    __half *Ah, *hH, *hWqkv, *hWo, *Kh, *Vh;
    cudaGetSymbolAddress((void**)&QKVp,  g_QKV);
    cudaGetSymbolAddress((void**)&Ah,    g_Ah);
    cudaGetSymbolAddress((void**)&hH,    g_hH);
    cudaGetSymbolAddress((void**)&hWqkv, g_hWqkv);
    cudaGetSymbolAddress((void**)&hWo,   g_hWo);
    cudaGetSymbolAddress((void**)&Kh,    g_Kh);
    cudaGetSymbolAddress((void**)&Vh,    g_Vh);

    float* Kp = QKVp + (size_t)32 * SEQ * HD;   // K head slots 32-39
    float* Vp = QKVp + (size_t)40 * SEQ * HD;   // V head slots 40-47

    cudaFuncSetAttribute(flash_v3, cudaFuncAttributeMaxDynamicSharedMemorySize,
                         F_SMEM);
    cudaFuncSetAttribute(gemm_f16, cudaFuncAttributeMaxDynamicSharedMemorySize,
                         G_SMEM);

    // fp16 pre-rounding (Wq|Wk|Wv into one concatenated buffer)
    const int nH4 = SEQ * HID / 4, nW4 = HID * HID / 4, nKV4 = NKV * HD * HID / 4;
    round_f16<<<nH4 / 256, 256>>>((const float4*)Hs, (__half2*)hH, nH4);
    round_f16<<<nW4 / 256, 256>>>((const float4*)Wq, (__half2*)hWqkv, nW4);
    round_f16<<<nKV4 / 256, 256>>>((const float4*)Wk,
        (__half2*)(hWqkv + (size_t)HID * HID), nKV4);
    round_f16<<<nKV4 / 256, 256>>>((const float4*)Wv,
        (__half2*)(hWqkv + (size_t)(HID + NKV * HD) * HID), nKV4);
    round_f16<<<nW4 / 256, 256>>>((const float4*)Wo, (__half2*)hWo, nW4);

    // single merged Q+K+V projection (N=6144, 768 CTAs), head-major scatter
    gemm_f16<<<dim3((HID + 2 * NKV * HD) / 256, SEQ / 128), 256, G_SMEM>>>(
        hH, hWqkv, QKVp, SEQ, HID + 2 * NKV * HD, HID, 1);

    rope_kernel<<<((NHEADS + NKV) * SEQ * 64) / 256, 256>>>(QKVp, Kp, Kh, pos);

    // V -> fp16
    const int nV4 = NKV * SEQ * HD / 4;
    round_f16<<<nV4 / 256, 256>>>((const float4*)Vp, (__half2*)Vh, nV4);

    // causal flash attention v3 (kv-tile 128, 1 CTA/SM)
    flash_v3<<<dim3(SEQ / 128, NHEADS), 256, F_SMEM>>>(QKVp, Kh, Vh, Ah);

    // output projection -> d_out fp32
    gemm_f16<<<dim3(HID / 256, SEQ / 128), 256, G_SMEM>>>(Ah, hWo, out,
                                                          SEQ, HID, HID, 0);
}